// round 1
// baseline (speedup 1.0000x reference)
#include <cuda_runtime.h>
#include <math.h>

// Problem dims
#define NROWS 8192
#define DDIM  1024

// Tiling
#define BM 128
#define BN 128
#define BK 32
#define TM 8
#define TN 8
#define NTHREADS 256   // 16x16 thread grid

// Scratch (allocation-free rule: __device__ globals)
__device__ float g_h[(size_t)NROWS * DDIM];          // 32 MB
__device__ float g_P[(size_t)NROWS * NROWS];         // 256 MB
__device__ float g_rowsum[NROWS];

// ---------------------------------------------------------------------------
// Shared GEMM mainloop. A is always K-major (row-major, K contiguous).
// B_KMAJOR=true  : B stored [n, k] K-contiguous (NT gemm, C = A * B^T)
// B_KMAJOR=false : B stored [k, n] N-contiguous (NN gemm, C = A * B)
// As/Bs are transposed to [BK][128] for conflict-light float4 compute reads.
// ---------------------------------------------------------------------------
template <bool B_KMAJOR>
__device__ __forceinline__ void gemm_mainloop(
    const float* __restrict__ Ag, size_t lda,
    const float* __restrict__ Bg, size_t ldb,
    int K, float acc[TM][TN],
    float (*As)[BM], float (*Bs)[BN],
    int tid, int tx, int ty)
{
    for (int k0 = 0; k0 < K; k0 += BK) {
        // Load A tile [BM rows x BK k] -> As[k][m] (transposed scatter)
        #pragma unroll
        for (int i = 0; i < 4; i++) {
            int f   = tid + i * NTHREADS;      // 0..1023
            int row = f >> 3;                  // 0..127
            int k4  = (f & 7) << 2;            // 0,4,...,28
            float4 v = *(const float4*)(Ag + (size_t)row * lda + k0 + k4);
            As[k4 + 0][row] = v.x;
            As[k4 + 1][row] = v.y;
            As[k4 + 2][row] = v.z;
            As[k4 + 3][row] = v.w;
        }
        if (B_KMAJOR) {
            #pragma unroll
            for (int i = 0; i < 4; i++) {
                int f   = tid + i * NTHREADS;
                int row = f >> 3;
                int k4  = (f & 7) << 2;
                float4 v = *(const float4*)(Bg + (size_t)row * ldb + k0 + k4);
                Bs[k4 + 0][row] = v.x;
                Bs[k4 + 1][row] = v.y;
                Bs[k4 + 2][row] = v.z;
                Bs[k4 + 3][row] = v.w;
            }
        } else {
            #pragma unroll
            for (int i = 0; i < 4; i++) {
                int f    = tid + i * NTHREADS;
                int krow = f >> 5;             // 0..31
                int n4   = (f & 31) << 2;      // 0..124
                float4 v = *(const float4*)(Bg + (size_t)(k0 + krow) * ldb + n4);
                *(float4*)&Bs[krow][n4] = v;
            }
        }
        __syncthreads();

        #pragma unroll
        for (int k = 0; k < BK; k++) {
            float ra[TM], rb[TN];
            *(float4*)&ra[0] = *(const float4*)&As[k][ty * TM];
            *(float4*)&ra[4] = *(const float4*)&As[k][ty * TM + 4];
            *(float4*)&rb[0] = *(const float4*)&Bs[k][tx * TN];
            *(float4*)&rb[4] = *(const float4*)&Bs[k][tx * TN + 4];
            #pragma unroll
            for (int i = 0; i < TM; i++)
                #pragma unroll
                for (int j = 0; j < TN; j++)
                    acc[i][j] = fmaf(ra[i], rb[j], acc[i][j]);
        }
        __syncthreads();
    }
}

// ---------------------------------------------------------------------------
// K1: h = x @ W^T + b     (NT gemm: both x and W are K-contiguous)
// ---------------------------------------------------------------------------
__global__ __launch_bounds__(NTHREADS)
void k1_linear(const float* __restrict__ X, const float* __restrict__ W,
               const float* __restrict__ bias)
{
    __shared__ float As[BK][BM];
    __shared__ float Bs[BK][BN];
    int tid = threadIdx.x;
    int tx = tid & 15, ty = tid >> 4;
    int bx = blockIdx.x, by = blockIdx.y;

    const float* Ag = X + (size_t)by * BM * DDIM;
    const float* Bg = W + (size_t)bx * BN * DDIM;

    float acc[TM][TN] = {};
    gemm_mainloop<true>(Ag, DDIM, Bg, DDIM, DDIM, acc, As, Bs, tid, tx, ty);

    int r0 = by * BM + ty * TM;
    int c0 = bx * BN + tx * TN;
    float bb[TN];
    *(float4*)&bb[0] = *(const float4*)&bias[c0];
    *(float4*)&bb[4] = *(const float4*)&bias[c0 + 4];

    #pragma unroll
    for (int i = 0; i < TM; i++) {
        float4 v0 = make_float4(acc[i][0] + bb[0], acc[i][1] + bb[1],
                                acc[i][2] + bb[2], acc[i][3] + bb[3]);
        float4 v1 = make_float4(acc[i][4] + bb[4], acc[i][5] + bb[5],
                                acc[i][6] + bb[6], acc[i][7] + bb[7]);
        float* dst = g_h + (size_t)(r0 + i) * DDIM + c0;
        *(float4*)dst       = v0;
        *(float4*)(dst + 4) = v1;
    }
}

// ---------------------------------------------------------------------------
// zero rowsum accumulator (re-run every replay)
// ---------------------------------------------------------------------------
__global__ void k_zero_rowsum()
{
    int i = blockIdx.x * blockDim.x + threadIdx.x;
    if (i < NROWS) g_rowsum[i] = 0.0f;
}

// ---------------------------------------------------------------------------
// K2: P = exp(tanh(h @ h^T)), symmetric (only upper-tri block grid computed),
//     with row-sum accumulation. No softmax max needed: tanh <= 1 bounds exp.
// ---------------------------------------------------------------------------
__global__ __launch_bounds__(NTHREADS)
void k2_scores()
{
    int bx = blockIdx.x;   // column block
    int by = blockIdx.y;   // row block
    if (by > bx) return;   // symmetry: compute upper triangle only

    __shared__ float As[BK][BM];
    __shared__ float Bs[BK][BN];
    __shared__ float scol[BN];

    int tid = threadIdx.x;
    int tx = tid & 15, ty = tid >> 4;
    if (tid < BN) scol[tid] = 0.0f;   // synced by first __syncthreads in mainloop

    const float* Ag = g_h + (size_t)by * BM * DDIM;
    const float* Bg = g_h + (size_t)bx * BN * DDIM;

    float acc[TM][TN] = {};
    gemm_mainloop<true>(Ag, DDIM, Bg, DDIM, DDIM, acc, As, Bs, tid, tx, ty);

    int r0 = by * BM + ty * TM;
    int c0 = bx * BN + tx * TN;

    float p[TM][TN];
    float rsum[TM] = {};
    float csum[TN] = {};
    #pragma unroll
    for (int i = 0; i < TM; i++)
        #pragma unroll
        for (int j = 0; j < TN; j++) {
            float v = __expf(tanhf(acc[i][j]));
            p[i][j] = v;
            rsum[i] += v;
            csum[j] += v;
        }

    // direct store (coalesced float4)
    #pragma unroll
    for (int i = 0; i < TM; i++) {
        float* dst = g_P + (size_t)(r0 + i) * NROWS + c0;
        *(float4*)dst       = make_float4(p[i][0], p[i][1], p[i][2], p[i][3]);
        *(float4*)(dst + 4) = make_float4(p[i][4], p[i][5], p[i][6], p[i][7]);
    }
    // mirror store for the symmetric block (scattered; accepted this round)
    if (bx != by) {
        #pragma unroll
        for (int j = 0; j < TN; j++) {
            float* dst = g_P + (size_t)(c0 + j) * NROWS + r0;
            #pragma unroll
            for (int i = 0; i < TM; i++) dst[i] = p[i][j];
        }
    }

    // row sums: reduce across the 16 tx lanes (contiguous within a warp)
    #pragma unroll
    for (int i = 0; i < TM; i++) {
        float v = rsum[i];
        v += __shfl_down_sync(0xffffffffu, v, 8, 16);
        v += __shfl_down_sync(0xffffffffu, v, 4, 16);
        v += __shfl_down_sync(0xffffffffu, v, 2, 16);
        v += __shfl_down_sync(0xffffffffu, v, 1, 16);
        if (tx == 0) atomicAdd(&g_rowsum[r0 + i], v);
    }

    // column sums feed the mirrored rows' rowsum (off-diagonal blocks only)
    if (bx != by) {
        #pragma unroll
        for (int j = 0; j < TN; j++)
            atomicAdd(&scol[tx * TN + j], csum[j]);
        __syncthreads();
        if (tid < BN) atomicAdd(&g_rowsum[bx * BN + tid], scol[tid]);
    }
}

// ---------------------------------------------------------------------------
// K3: out = tanh( (P @ h) / rowsum )   (NN gemm: P K-contig, h N-contig)
// ---------------------------------------------------------------------------
__global__ __launch_bounds__(NTHREADS)
void k3_out(float* __restrict__ out)
{
    __shared__ float As[BK][BM];
    __shared__ float Bs[BK][BN];
    int tid = threadIdx.x;
    int tx = tid & 15, ty = tid >> 4;
    int bx = blockIdx.x, by = blockIdx.y;

    const float* Ag = g_P + (size_t)by * BM * NROWS;
    const float* Bg = g_h + (size_t)bx * BN;   // (k=0, col block) base

    float acc[TM][TN] = {};
    gemm_mainloop<false>(Ag, NROWS, Bg, DDIM, NROWS, acc, As, Bs, tid, tx, ty);

    int r0 = by * BM + ty * TM;
    int c0 = bx * BN + tx * TN;
    #pragma unroll
    for (int i = 0; i < TM; i++) {
        float inv = 1.0f / g_rowsum[r0 + i];
        float4 v0 = make_float4(tanhf(acc[i][0] * inv), tanhf(acc[i][1] * inv),
                                tanhf(acc[i][2] * inv), tanhf(acc[i][3] * inv));
        float4 v1 = make_float4(tanhf(acc[i][4] * inv), tanhf(acc[i][5] * inv),
                                tanhf(acc[i][6] * inv), tanhf(acc[i][7] * inv));
        float* dst = out + (size_t)(r0 + i) * DDIM + c0;
        *(float4*)dst       = v0;
        *(float4*)(dst + 4) = v1;
    }
}

// ---------------------------------------------------------------------------
extern "C" void kernel_launch(void* const* d_in, const int* in_sizes, int n_in,
                              void* d_out, int out_size)
{
    const float* x = (const float*)d_in[0];   // [8192, 1024]
    const float* W = (const float*)d_in[1];   // [1024, 1024]
    const float* b = (const float*)d_in[2];   // [1024]
    float* out = (float*)d_out;               // [8192, 1024]

    dim3 t(NTHREADS);
    k1_linear<<<dim3(DDIM / BN, NROWS / BM), t>>>(x, W, b);
    k_zero_rowsum<<<NROWS / 256, 256>>>();
    k2_scores<<<dim3(NROWS / BN, NROWS / BM), t>>>();
    k3_out<<<dim3(DDIM / BN, NROWS / BM), t>>>(out);
}